// round 2
// baseline (speedup 1.0000x reference)
#include <cuda_runtime.h>
#include <math.h>

#define B   8
#define LQ  2048
#define LKV 2048
#define D   128
#define DV  128

// Tiling for both GEMMs: 64x64 output tile, K-chunk 32, 256 threads, 4x4 per thread.
#define BM 64
#define BN 64
#define BK 32
#define SPAD 4   // smem row padding (keeps 16B alignment: row stride 68 floats = 272B)

// ---------------------------------------------------------------------------
// GEMM1: S[b,m,n] = scale * sum_d Q[b,m,d] * K[b,n,d]   (NT, both K-major)
// ---------------------------------------------------------------------------
__global__ __launch_bounds__(256) void gemm_qk_kernel(
    const float* __restrict__ Q, const float* __restrict__ K,
    float* __restrict__ S)
{
    __shared__ float Qs[BK][BM + SPAD];
    __shared__ float Ks[BK][BN + SPAD];

    const int b  = blockIdx.z;
    const int m0 = blockIdx.y * BM;
    const int n0 = blockIdx.x * BN;

    const float* Qb = Q + (size_t)b * LQ  * D;
    const float* Kb = K + (size_t)b * LKV * D;
    float*       Sb = S + (size_t)b * LQ  * LKV;

    const int tid = threadIdx.x;
    const int tx  = tid & 15;   // n-tile coord
    const int ty  = tid >> 4;   // m-tile coord

    // staging coords: 256 threads load 64x32 floats (512 float4) in 2 steps
    const int lr = tid >> 3;        // 0..31  row within 32-row chunk
    const int lc = (tid & 7) * 4;   // 0..28  k offset

    float acc[4][4] = {};

    for (int k0 = 0; k0 < D; k0 += BK) {
        #pragma unroll
        for (int s = 0; s < 2; s++) {
            int m = lr + s * 32;
            float4 v = *(const float4*)(Qb + (size_t)(m0 + m) * D + k0 + lc);
            Qs[lc + 0][m] = v.x; Qs[lc + 1][m] = v.y;
            Qs[lc + 2][m] = v.z; Qs[lc + 3][m] = v.w;
            float4 w = *(const float4*)(Kb + (size_t)(n0 + m) * D + k0 + lc);
            Ks[lc + 0][m] = w.x; Ks[lc + 1][m] = w.y;
            Ks[lc + 2][m] = w.z; Ks[lc + 3][m] = w.w;
        }
        __syncthreads();

        #pragma unroll
        for (int kk = 0; kk < BK; kk++) {
            float a[4], c[4];
            *(float4*)a = *(const float4*)&Qs[kk][ty * 4];
            *(float4*)c = *(const float4*)&Ks[kk][tx * 4];
            #pragma unroll
            for (int i = 0; i < 4; i++)
                #pragma unroll
                for (int j = 0; j < 4; j++)
                    acc[i][j] += a[i] * c[j];
        }
        __syncthreads();
    }

    const float scale = 0.08838834764831845f;  // 1/sqrt(128)
    #pragma unroll
    for (int i = 0; i < 4; i++) {
        float4 o;
        o.x = acc[i][0] * scale; o.y = acc[i][1] * scale;
        o.z = acc[i][2] * scale; o.w = acc[i][3] * scale;
        *(float4*)(Sb + (size_t)(m0 + ty * 4 + i) * LKV + n0 + tx * 4) = o;
    }
}

// ---------------------------------------------------------------------------
// Softmax: one block per row (2048 floats), in place.
// ---------------------------------------------------------------------------
__global__ __launch_bounds__(256) void softmax_kernel(float* __restrict__ S)
{
    __shared__ float red_max[8];
    __shared__ float red_sum[8];

    float* r = S + (size_t)blockIdx.x * LKV;
    const int tid  = threadIdx.x;
    const int lane = tid & 31;
    const int warp = tid >> 5;

    float4 a = *(const float4*)(r + tid * 4);
    float4 c = *(const float4*)(r + 1024 + tid * 4);

    float m = fmaxf(fmaxf(fmaxf(a.x, a.y), fmaxf(a.z, a.w)),
                    fmaxf(fmaxf(c.x, c.y), fmaxf(c.z, c.w)));
    #pragma unroll
    for (int o = 16; o > 0; o >>= 1) m = fmaxf(m, __shfl_xor_sync(0xffffffffu, m, o));
    if (lane == 0) red_max[warp] = m;
    __syncthreads();
    m = red_max[0];
    #pragma unroll
    for (int i = 1; i < 8; i++) m = fmaxf(m, red_max[i]);

    a.x = expf(a.x - m); a.y = expf(a.y - m); a.z = expf(a.z - m); a.w = expf(a.w - m);
    c.x = expf(c.x - m); c.y = expf(c.y - m); c.z = expf(c.z - m); c.w = expf(c.w - m);

    float s = a.x + a.y + a.z + a.w + c.x + c.y + c.z + c.w;
    #pragma unroll
    for (int o = 16; o > 0; o >>= 1) s += __shfl_xor_sync(0xffffffffu, s, o);
    if (lane == 0) red_sum[warp] = s;
    __syncthreads();
    s = red_sum[0];
    #pragma unroll
    for (int i = 1; i < 8; i++) s += red_sum[i];

    const float inv = 1.0f / s;
    a.x *= inv; a.y *= inv; a.z *= inv; a.w *= inv;
    c.x *= inv; c.y *= inv; c.z *= inv; c.w *= inv;

    *(float4*)(r + tid * 4)        = a;
    *(float4*)(r + 1024 + tid * 4) = c;
}

// ---------------------------------------------------------------------------
// GEMM2: C[b,m,v] = sum_k W[b,m,k] * V[b,k,v]   (NN)
// ---------------------------------------------------------------------------
__global__ __launch_bounds__(256) void gemm_pv_kernel(
    const float* __restrict__ W, const float* __restrict__ V,
    float* __restrict__ C)
{
    __shared__ float Ws[BK][BM + SPAD];
    __shared__ float Vs[BK][BN + SPAD];

    const int b  = blockIdx.z;
    const int m0 = blockIdx.y * BM;
    const int n0 = blockIdx.x * BN;

    const float* Wb = W + (size_t)b * LQ  * LKV;
    const float* Vb = V + (size_t)b * LKV * DV;
    float*       Cb = C + (size_t)b * LQ  * DV;

    const int tid = threadIdx.x;
    const int tx  = tid & 15;
    const int ty  = tid >> 4;

    const int lr = tid >> 3;        // W staging: row 0..31
    const int lc = (tid & 7) * 4;   // W staging: k offset
    const int vr = tid >> 4;        // V staging: row 0..15
    const int vc = (tid & 15) * 4;  // V staging: col offset

    float acc[4][4] = {};

    for (int k0 = 0; k0 < LKV; k0 += BK) {
        #pragma unroll
        for (int s = 0; s < 2; s++) {
            int m = lr + s * 32;
            float4 w = *(const float4*)(Wb + (size_t)(m0 + m) * LKV + k0 + lc);
            Ws[lc + 0][m] = w.x; Ws[lc + 1][m] = w.y;
            Ws[lc + 2][m] = w.z; Ws[lc + 3][m] = w.w;
            int kr = vr + s * 16;
            float4 v = *(const float4*)(Vb + (size_t)(k0 + kr) * DV + n0 + vc);
            *(float4*)&Vs[kr][vc] = v;
        }
        __syncthreads();

        #pragma unroll
        for (int kk = 0; kk < BK; kk++) {
            float a[4], c[4];
            *(float4*)a = *(const float4*)&Ws[kk][ty * 4];
            *(float4*)c = *(const float4*)&Vs[kk][tx * 4];
            #pragma unroll
            for (int i = 0; i < 4; i++)
                #pragma unroll
                for (int j = 0; j < 4; j++)
                    acc[i][j] += a[i] * c[j];
        }
        __syncthreads();
    }

    #pragma unroll
    for (int i = 0; i < 4; i++) {
        float4 o;
        o.x = acc[i][0]; o.y = acc[i][1]; o.z = acc[i][2]; o.w = acc[i][3];
        *(float4*)(Cb + (size_t)(m0 + ty * 4 + i) * DV + n0 + tx * 4) = o;
    }
}

// ---------------------------------------------------------------------------
extern "C" void kernel_launch(void* const* d_in, const int* in_sizes, int n_in,
                              void* d_out, int out_size)
{
    const float* Q = (const float*)d_in[0];
    const float* K = (const float*)d_in[1];
    const float* V = (const float*)d_in[2];

    float* Wout = (float*)d_out;                         // attention weights (B,LQ,LKV)
    float* Cout = Wout + (size_t)B * LQ * LKV;           // context (B,LQ,DV)

    dim3 g1(LKV / BN, LQ / BM, B);          // 32 x 32 x 8
    gemm_qk_kernel<<<g1, 256>>>(Q, K, Wout);

    softmax_kernel<<<B * LQ, 256>>>(Wout);  // 16384 rows

    dim3 g2(DV / BN, LQ / BM, B);           // 2 x 32 x 8
    gemm_pv_kernel<<<g2, 256>>>(Wout, V, Cout);
}

// round 4
// speedup vs baseline: 2.6757x; 2.6757x over previous
#include <cuda_runtime.h>
#include <cuda_bf16.h>
#include <cstdint>

static constexpr int BATCH = 8;
static constexpr int LQ    = 2048;
static constexpr int LKV   = 2048;
static constexpr int DIM   = 128;   // D == DV == 128
static constexpr float SM_SCALE = 0.08838834764831845f; // 1/sqrt(128)

// Scratch (device globals; no runtime allocation allowed)
__device__ __align__(128) __nv_bfloat16 g_Vt_hi[(size_t)BATCH * DIM * LKV]; // [B][DV][LKV]
__device__ __align__(128) __nv_bfloat16 g_Vt_lo[(size_t)BATCH * DIM * LKV];
__device__ __align__(128) __nv_bfloat16 g_Wh[(size_t)BATCH * LQ * LKV];     // [B][LQ][LKV]
__device__ __align__(128) __nv_bfloat16 g_Wl[(size_t)BATCH * LQ * LKV];

// ---------------------------------------------------------------------------
// Helpers (compute_103-safe: ldmatrix / mma.sync / cp.async only)
// ---------------------------------------------------------------------------
__device__ __forceinline__ uint32_t smem_u32(const void* p) {
    uint32_t a;
    asm("{ .reg .u64 t; cvta.to.shared.u64 t, %1; cvt.u32.u64 %0, t; }"
        : "=r"(a) : "l"(p));
    return a;
}
__device__ __forceinline__ uint32_t swz(uint32_t off) {       // SW128 swizzle
    return off ^ ((off >> 3) & 0x70);
}
__device__ __forceinline__ uint32_t pack2(__nv_bfloat16 a, __nv_bfloat16 b) {
    __nv_bfloat162 t(a, b);
    return *reinterpret_cast<uint32_t*>(&t);
}
__device__ __forceinline__ void split1(float v, __nv_bfloat16& h, __nv_bfloat16& l) {
    h = __float2bfloat16(v);
    l = __float2bfloat16(v - __bfloat162float(h));
}
__device__ __forceinline__ void split4(float4 v, uint2& hi, uint2& lo) {
    __nv_bfloat16 h0, h1, h2, h3, l0, l1, l2, l3;
    split1(v.x, h0, l0); split1(v.y, h1, l1);
    split1(v.z, h2, l2); split1(v.w, h3, l3);
    hi.x = pack2(h0, h1); hi.y = pack2(h2, h3);
    lo.x = pack2(l0, l1); lo.y = pack2(l2, l3);
}
__device__ __forceinline__ void sts8(uint32_t addr, uint2 v) {
    asm volatile("st.shared.v2.b32 [%0], {%1, %2};" :: "r"(addr), "r"(v.x), "r"(v.y) : "memory");
}
__device__ __forceinline__ void ldsm4(uint32_t* r, uint32_t addr) {
    asm volatile("ldmatrix.sync.aligned.m8n8.x4.shared.b16 {%0,%1,%2,%3}, [%4];"
                 : "=r"(r[0]), "=r"(r[1]), "=r"(r[2]), "=r"(r[3]) : "r"(addr));
}
__device__ __forceinline__ void mma_bf16(float* d, const uint32_t* a, const uint32_t* b) {
    asm volatile("mma.sync.aligned.m16n8k16.row.col.f32.bf16.bf16.f32 "
                 "{%0,%1,%2,%3}, {%4,%5,%6,%7}, {%8,%9}, {%0,%1,%2,%3};"
                 : "+f"(d[0]), "+f"(d[1]), "+f"(d[2]), "+f"(d[3])
                 : "r"(a[0]), "r"(a[1]), "r"(a[2]), "r"(a[3]), "r"(b[0]), "r"(b[1]));
}
#define CP_ASYNC16(dst, src) \
    asm volatile("cp.async.cg.shared.global [%0], [%1], 16;" :: "r"(dst), "l"(src) : "memory")
#define CP_COMMIT()  asm volatile("cp.async.commit_group;" ::: "memory")
#define CP_WAIT(n)   asm volatile("cp.async.wait_group %0;" :: "n"(n) : "memory")

// ---------------------------------------------------------------------------
// Kernel 0: transpose + bf16-split V:  V[b][k][n] -> Vt_hi/lo[b][n][k]
// ---------------------------------------------------------------------------
__global__ __launch_bounds__(256) void vt_split_kernel(const float* __restrict__ V)
{
    __shared__ float t[32][33];
    const int b  = blockIdx.z;
    const int k0 = blockIdx.y * 32;
    const int n0 = blockIdx.x * 32;
    const int tx = threadIdx.x & 31;
    const int ty = threadIdx.x >> 5;   // 0..7

    #pragma unroll
    for (int i = 0; i < 4; i++) {
        int k = ty + i * 8;
        t[k][tx] = V[((size_t)b * LKV + k0 + k) * DIM + n0 + tx];
    }
    __syncthreads();
    #pragma unroll
    for (int i = 0; i < 4; i++) {
        int n = ty + i * 8;
        float x = t[tx][n];
        __nv_bfloat16 h, l;
        split1(x, h, l);
        size_t o = ((size_t)b * DIM + n0 + n) * LKV + k0 + tx;
        g_Vt_hi[o] = h;
        g_Vt_lo[o] = l;
    }
}

// ---------------------------------------------------------------------------
// GEMM1: S = (Q*scale) K^T via mma.sync bf16x3.  CTA tile 128x128, 8 warps
// (warp tile 32x64).  K=128 in 2 chunks of 64.  SW128 smem, 16KB/tile.
// ---------------------------------------------------------------------------
static constexpr int G1_SMEM = 1024 + 4 * 16384;

__global__ __launch_bounds__(256, 2) void gemm1_mma_kernel(
    const float* __restrict__ Q, const float* __restrict__ K,
    float* __restrict__ S)
{
    extern __shared__ char smem[];
    const uint32_t sb = (smem_u32(smem) + 1023u) & ~1023u;
    const uint32_t QH = sb;
    const uint32_t QL = QH + 16384;
    const uint32_t KH = QL + 16384;
    const uint32_t KL = KH + 16384;

    const int tid  = threadIdx.x;
    const int lane = tid & 31;
    const int w    = tid >> 5;
    const int wm   = (w >> 1) * 32;   // warp M offset (4 warps in M)
    const int wn   = (w & 1) * 64;    // warp N offset (2 warps in N)

    const int b  = blockIdx.z;
    const int m0 = blockIdx.y * 128;
    const int n0 = blockIdx.x * 128;

    const float* Qb = Q + (size_t)b * LQ  * DIM;
    const float* Kb = K + (size_t)b * LKV * DIM;
    float*       Sb = S + (size_t)b * LQ  * LKV;

    float acc[2][8][4] = {};

    // ldmatrix lane address components
    const uint32_t a_row = lane & 15;             // A: rows 0..15
    const uint32_t a_kof = (lane >> 4) * 16;      // A: +0 / +8 cols (bytes: *2)
    const uint32_t b_row = (lane & 7) + ((lane & 16) >> 1);  // B: n row
    const uint32_t b_kof = ((lane >> 3) & 1) * 16;           // B: +0 / +8 cols (bytes)

    for (int c = 0; c < 2; c++) {
        const int k0 = c * 64;
        if (c) __syncthreads();   // smem reuse

        // load + split 128x64 Q and K (2048 float4, 256 threads -> 8 iters)
        #pragma unroll
        for (int i = 0; i < 8; i++) {
            int idx = i * 256 + tid;
            int row = idx >> 4;
            int c4  = (idx & 15) * 4;
            uint32_t off = swz((uint32_t)row * 128u + (uint32_t)c4 * 2u);

            float4 q = *(const float4*)(Qb + (size_t)(m0 + row) * DIM + k0 + c4);
            q.x *= SM_SCALE; q.y *= SM_SCALE; q.z *= SM_SCALE; q.w *= SM_SCALE;
            uint2 qh, ql; split4(q, qh, ql);
            sts8(QH + off, qh);
            sts8(QL + off, ql);

            float4 kv = *(const float4*)(Kb + (size_t)(n0 + row) * DIM + k0 + c4);
            uint2 kh, kl; split4(kv, kh, kl);
            sts8(KH + off, kh);
            sts8(KL + off, kl);
        }
        __syncthreads();

        #pragma unroll
        for (int ks = 0; ks < 4; ks++) {
            const uint32_t kb = ks * 32;   // byte offset of k16 step
            uint32_t ah[2][4], al[2][4], bb[8][2];

            #pragma unroll
            for (int mf = 0; mf < 2; mf++) {
                uint32_t ro = (uint32_t)(wm + mf * 16 + a_row) * 128u + kb + a_kof;
                ldsm4(ah[mf], QH + swz(ro));
                ldsm4(al[mf], QL + swz(ro));
            }
            #pragma unroll
            for (int j = 0; j < 4; j++) {
                uint32_t ro = (uint32_t)(wn + j * 16 + b_row) * 128u + kb + b_kof;
                ldsm4(&bb[2 * j][0], KH + swz(ro));
            }
            #pragma unroll
            for (int mf = 0; mf < 2; mf++)
                #pragma unroll
                for (int nf = 0; nf < 8; nf++) {
                    mma_bf16(acc[mf][nf], ah[mf], bb[nf]);
                    mma_bf16(acc[mf][nf], al[mf], bb[nf]);
                }
            #pragma unroll
            for (int j = 0; j < 4; j++) {
                uint32_t ro = (uint32_t)(wn + j * 16 + b_row) * 128u + kb + b_kof;
                ldsm4(&bb[2 * j][0], KL + swz(ro));
            }
            #pragma unroll
            for (int mf = 0; mf < 2; mf++)
                #pragma unroll
                for (int nf = 0; nf < 8; nf++)
                    mma_bf16(acc[mf][nf], ah[mf], bb[nf]);
        }
    }

    // epilogue: thread holds (row lane/4 [+8], col 2*(lane%4) [+1]) per frag
    const int er = lane >> 2;
    const int ec = (lane & 3) * 2;
    #pragma unroll
    for (int mf = 0; mf < 2; mf++)
        #pragma unroll
        for (int nf = 0; nf < 8; nf++) {
            int r = m0 + wm + mf * 16 + er;
            int cc = n0 + wn + nf * 8 + ec;
            *(float2*)(Sb + (size_t)r * LKV + cc)       = make_float2(acc[mf][nf][0], acc[mf][nf][1]);
            *(float2*)(Sb + (size_t)(r + 8) * LKV + cc) = make_float2(acc[mf][nf][2], acc[mf][nf][3]);
        }
}

// ---------------------------------------------------------------------------
// Softmax (in place) + fused bf16 hi/lo split of W into scratch.
// ---------------------------------------------------------------------------
__global__ __launch_bounds__(256) void softmax_split_kernel(float* __restrict__ S)
{
    __shared__ float red_max[8];
    __shared__ float red_sum[8];

    const size_t row = blockIdx.x;
    float* r = S + row * LKV;
    const int tid  = threadIdx.x;
    const int lane = tid & 31;
    const int warp = tid >> 5;

    float4 a = *(const float4*)(r + tid * 4);
    float4 c = *(const float4*)(r + 1024 + tid * 4);

    float m = fmaxf(fmaxf(fmaxf(a.x, a.y), fmaxf(a.z, a.w)),
                    fmaxf(fmaxf(c.x, c.y), fmaxf(c.z, c.w)));
    #pragma unroll
    for (int o = 16; o > 0; o >>= 1) m = fmaxf(m, __shfl_xor_sync(0xffffffffu, m, o));
    if (lane == 0) red_max[warp] = m;
    __syncthreads();
    m = red_max[0];
    #pragma unroll
    for (int i = 1; i < 8; i++) m = fmaxf(m, red_max[i]);

    a.x = expf(a.x - m); a.y = expf(a.y - m); a.z = expf(a.z - m); a.w = expf(a.w - m);
    c.x = expf(c.x - m); c.y = expf(c.y - m); c.z = expf(c.z - m); c.w = expf(c.w - m);

    float s = a.x + a.y + a.z + a.w + c.x + c.y + c.z + c.w;
    #pragma unroll
    for (int o = 16; o > 0; o >>= 1) s += __shfl_xor_sync(0xffffffffu, s, o);
    if (lane == 0) red_sum[warp] = s;
    __syncthreads();
    s = red_sum[0];
    #pragma unroll
    for (int i = 1; i < 8; i++) s += red_sum[i];

    const float inv = 1.0f / s;
    a.x *= inv; a.y *= inv; a.z *= inv; a.w *= inv;
    c.x *= inv; c.y *= inv; c.z *= inv; c.w *= inv;

    *(float4*)(r + tid * 4)        = a;
    *(float4*)(r + 1024 + tid * 4) = c;

    // fused bf16 split -> scratch for GEMM2
    uint2 h, l;
    split4(a, h, l);
    *(uint2*)(g_Wh + row * LKV + tid * 4) = h;
    *(uint2*)(g_Wl + row * LKV + tid * 4) = l;
    split4(c, h, l);
    *(uint2*)(g_Wh + row * LKV + 1024 + tid * 4) = h;
    *(uint2*)(g_Wl + row * LKV + 1024 + tid * 4) = l;
}

// ---------------------------------------------------------------------------
// GEMM2: C = W V via mma.sync bf16x3.  CTA tile 128x128 (full DV), K=2048
// in 32 chunks of 64.  All operands bf16 in gmem -> cp.async double buffer.
// ---------------------------------------------------------------------------
static constexpr int G2_SMEM = 1024 + 2 * 4 * 16384;   // 2 bufs x (Wh,Wl,Vh,Vl)

__global__ __launch_bounds__(256, 1) void gemm2_mma_kernel(float* __restrict__ C)
{
    extern __shared__ char smem[];
    const uint32_t sb = (smem_u32(smem) + 1023u) & ~1023u;

    const int tid  = threadIdx.x;
    const int lane = tid & 31;
    const int w    = tid >> 5;
    const int wm   = (w >> 1) * 32;
    const int wn   = (w & 1) * 64;

    const int m0 = blockIdx.x * 128;
    const int b  = blockIdx.y;

    const __nv_bfloat16* Wh = g_Wh + ((size_t)b * LQ + m0) * LKV;
    const __nv_bfloat16* Wl = g_Wl + ((size_t)b * LQ + m0) * LKV;
    const __nv_bfloat16* Vh = g_Vt_hi + (size_t)b * DIM * LKV;
    const __nv_bfloat16* Vl = g_Vt_lo + (size_t)b * DIM * LKV;
    float* Cb = C + (size_t)b * LQ * DIM;

    // tile loader: 4 tiles of 128 rows x 64 bf16 (16KB, 1024 x 16B units)
    auto load_chunk = [&](int c, int buf) {
        const int k0 = c * 64;
        const uint32_t base = sb + (uint32_t)buf * 4u * 16384u;
        #pragma unroll
        for (int u = 0; u < 4; u++) {
            int unit = u * 256 + tid;
            int row  = unit >> 3;
            int col8 = (unit & 7) * 8;
            uint32_t off = swz((uint32_t)row * 128u + (uint32_t)col8 * 2u);
            CP_ASYNC16(base + off,             Wh + (size_t)row * LKV + k0 + col8);
            CP_ASYNC16(base + 16384u + off,    Wl + (size_t)row * LKV + k0 + col8);
            CP_ASYNC16(base + 32768u + off,    Vh + (size_t)row * LKV + k0 + col8);
            CP_ASYNC16(base + 49152u + off,    Vl + (size_t)row * LKV + k0 + col8);
        }
    };

    float acc[2][8][4] = {};

    const uint32_t a_row = lane & 15;
    const uint32_t a_kof = (lane >> 4) * 16;
    const uint32_t b_row = (lane & 7) + ((lane & 16) >> 1);
    const uint32_t b_kof = ((lane >> 3) & 1) * 16;

    load_chunk(0, 0);
    CP_COMMIT();

    for (int c = 0; c < 32; c++) {
        if (c < 31) {
            load_chunk(c + 1, (c + 1) & 1);
            CP_COMMIT();
            CP_WAIT(1);
        } else {
            CP_WAIT(0);
        }
        __syncthreads();

        const uint32_t base = sb + (uint32_t)(c & 1) * 4u * 16384u;
        const uint32_t WHt = base, WLt = base + 16384u;
        const uint32_t VHt = base + 32768u, VLt = base + 49152u;

        #pragma unroll
        for (int ks = 0; ks < 4; ks++) {
            const uint32_t kb = ks * 32;
            uint32_t ah[2][4], al[2][4], bb[8][2];

            #pragma unroll
            for (int mf = 0; mf < 2; mf++) {
                uint32_t ro = (uint32_t)(wm + mf * 16 + a_row) * 128u + kb + a_kof;
                ldsm4(ah[mf], WHt + swz(ro));
                ldsm4(al[mf], WLt + swz(ro));
            }
            #pragma unroll
            for (int j = 0; j < 4; j++) {
                uint32_t ro = (uint32_t)(wn + j * 16 + b_row) * 128u + kb + b_kof;
                ldsm4(&bb[2 * j][0], VHt + swz(ro));
            }
            #pragma unroll
            for (int mf = 0; mf < 2; mf++)
                #pragma unroll
                for (int nf = 0; nf < 8; nf++) {
                    mma_bf16(acc[mf][nf], ah[mf], bb[nf]);
                    mma_bf16(acc[mf][nf], al[mf], bb[nf]);
                }
            #pragma unroll
            for (int j = 0; j < 4; j++) {
                uint32_t ro = (uint32_t)(wn + j * 16 + b_row) * 128u + kb + b_kof;
                ldsm4(&bb[2 * j][0], VLt + swz(ro));
            }
            #pragma unroll
            for (int mf = 0; mf < 2; mf++)
                #pragma unroll
                for (int nf = 0; nf < 8; nf++)
                    mma_bf16(acc[mf][nf], ah[mf], bb[nf]);
        }
        __syncthreads();
    }

    const int er = lane >> 2;
    const int ec = (lane & 3) * 2;
    #pragma unroll
    for (int mf = 0; mf < 2; mf++)
        #pragma unroll
        for (int nf = 0; nf < 8; nf++) {
            int r = m0 + wm + mf * 16 + er;
            int cc = wn + nf * 8 + ec;
            *(float2*)(Cb + (size_t)r * DIM + cc)       = make_float2(acc[mf][nf][0], acc[mf][nf][1]);
            *(float2*)(Cb + (size_t)(r + 8) * DIM + cc) = make_float2(acc[mf][nf][2], acc[mf][nf][3]);
        }
}

// ---------------------------------------------------------------------------
extern "C" void kernel_launch(void* const* d_in, const int* in_sizes, int n_in,
                              void* d_out, int out_size)
{
    const float* Q = (const float*)d_in[0];
    const float* K = (const float*)d_in[1];
    const float* V = (const float*)d_in[2];

    float* Wout = (float*)d_out;                            // (B,LQ,LKV)
    float* Cout = Wout + (size_t)BATCH * LQ * LKV;          // (B,LQ,DV)

    static bool attr_done = false;
    if (!attr_done) {
        cudaFuncSetAttribute(gemm1_mma_kernel,
            cudaFuncAttributeMaxDynamicSharedMemorySize, G1_SMEM);
        cudaFuncSetAttribute(gemm2_mma_kernel,
            cudaFuncAttributeMaxDynamicSharedMemorySize, G2_SMEM);
        attr_done = true;
    }

    dim3 gt(DIM / 32, LKV / 32, BATCH);
    vt_split_kernel<<<gt, 256>>>(V);

    dim3 g1(LKV / 128, LQ / 128, BATCH);    // 16 x 16 x 8 = 2048 CTAs
    gemm1_mma_kernel<<<g1, 256, G1_SMEM>>>(Q, K, Wout);

    softmax_split_kernel<<<BATCH * LQ, 256>>>(Wout);

    dim3 g2(LQ / 128, BATCH);               // 16 x 8 = 128 CTAs
    gemm2_mma_kernel<<<g2, 256, G2_SMEM>>>(Cout);
}

// round 7
// speedup vs baseline: 2.8686x; 1.0721x over previous
#include <cuda_runtime.h>
#include <cuda_bf16.h>
#include <cstdint>

static constexpr int BATCH = 8;
static constexpr int LQ    = 2048;
static constexpr int LKV   = 2048;
static constexpr int DIM   = 128;   // D == DV == 128
static constexpr float SM_SCALE = 0.08838834764831845f; // 1/sqrt(128)

// Scratch (device globals; no runtime allocation allowed)
__device__ __align__(128) __nv_bfloat16 g_Vt_hi[(size_t)BATCH * DIM * LKV]; // [B][DV][LKV]
__device__ __align__(128) __nv_bfloat16 g_Vt_lo[(size_t)BATCH * DIM * LKV];
// per-row partial exp-sums: [B*LQ][32]  (16 n-tiles x 2 n-warps), deterministic
__device__ __align__(128) float g_partial[(size_t)BATCH * LQ * 32];

// ---------------------------------------------------------------------------
// Helpers (compute_103-safe: ldmatrix / mma.sync / cp.async only)
// ---------------------------------------------------------------------------
__device__ __forceinline__ uint32_t smem_u32(const void* p) {
    uint32_t a;
    asm("{ .reg .u64 t; cvta.to.shared.u64 t, %1; cvt.u32.u64 %0, t; }"
        : "=r"(a) : "l"(p));
    return a;
}
__device__ __forceinline__ uint32_t swz(uint32_t off) {       // SW128 swizzle
    return off ^ ((off >> 3) & 0x70);
}
__device__ __forceinline__ uint32_t pack2(__nv_bfloat16 a, __nv_bfloat16 b) {
    __nv_bfloat162 t(a, b);
    return *reinterpret_cast<uint32_t*>(&t);
}
__device__ __forceinline__ void split1(float v, __nv_bfloat16& h, __nv_bfloat16& l) {
    h = __float2bfloat16(v);
    l = __float2bfloat16(v - __bfloat162float(h));
}
__device__ __forceinline__ void split4(float4 v, uint2& hi, uint2& lo) {
    __nv_bfloat16 h0, h1, h2, h3, l0, l1, l2, l3;
    split1(v.x, h0, l0); split1(v.y, h1, l1);
    split1(v.z, h2, l2); split1(v.w, h3, l3);
    hi.x = pack2(h0, h1); hi.y = pack2(h2, h3);
    lo.x = pack2(l0, l1); lo.y = pack2(l2, l3);
}
__device__ __forceinline__ void sts8(uint32_t addr, uint2 v) {
    asm volatile("st.shared.v2.b32 [%0], {%1, %2};" :: "r"(addr), "r"(v.x), "r"(v.y) : "memory");
}
__device__ __forceinline__ void ldsm4(uint32_t* r, uint32_t addr) {
    asm volatile("ldmatrix.sync.aligned.m8n8.x4.shared.b16 {%0,%1,%2,%3}, [%4];"
                 : "=r"(r[0]), "=r"(r[1]), "=r"(r[2]), "=r"(r[3]) : "r"(addr));
}
__device__ __forceinline__ void mma_bf16(float* d, const uint32_t* a, const uint32_t* b) {
    asm volatile("mma.sync.aligned.m16n8k16.row.col.f32.bf16.bf16.f32 "
                 "{%0,%1,%2,%3}, {%4,%5,%6,%7}, {%8,%9}, {%0,%1,%2,%3};"
                 : "+f"(d[0]), "+f"(d[1]), "+f"(d[2]), "+f"(d[3])
                 : "r"(a[0]), "r"(a[1]), "r"(a[2]), "r"(a[3]), "r"(b[0]), "r"(b[1]));
}
#define CP_ASYNC16(dst, src) \
    asm volatile("cp.async.cg.shared.global [%0], [%1], 16;" :: "r"(dst), "l"(src) : "memory")
#define CP_COMMIT()  asm volatile("cp.async.commit_group;" ::: "memory")
#define CP_WAIT(n)   asm volatile("cp.async.wait_group %0;" :: "n"(n) : "memory")

// ---------------------------------------------------------------------------
// Kernel 0: transpose + bf16-split V:  V[b][k][n] -> Vt_hi/lo[b][n][k]
// ---------------------------------------------------------------------------
__global__ __launch_bounds__(256) void vt_split_kernel(const float* __restrict__ V)
{
    __shared__ float t[32][33];
    const int b  = blockIdx.z;
    const int k0 = blockIdx.y * 32;
    const int n0 = blockIdx.x * 32;
    const int tx = threadIdx.x & 31;
    const int ty = threadIdx.x >> 5;   // 0..7

    #pragma unroll
    for (int i = 0; i < 4; i++) {
        int k = ty + i * 8;
        t[k][tx] = V[((size_t)b * LKV + k0 + k) * DIM + n0 + tx];
    }
    __syncthreads();
    #pragma unroll
    for (int i = 0; i < 4; i++) {
        int n = ty + i * 8;
        float x = t[tx][n];
        __nv_bfloat16 h, l;
        split1(x, h, l);
        size_t o = ((size_t)b * DIM + n0 + n) * LKV + k0 + tx;
        g_Vt_hi[o] = h;
        g_Vt_lo[o] = l;
    }
}

// ---------------------------------------------------------------------------
// GEMM1: E = exp((Q*scale) K^T) via mma.sync bf16x3.  CTA tile 128x128,
// 8 warps (warp tile 32x64).  Writes unnormalized E + per-row partial sums.
// ---------------------------------------------------------------------------
static constexpr int G1_SMEM = 1024 + 4 * 16384;

__global__ __launch_bounds__(256, 2) void gemm1_mma_kernel(
    const float* __restrict__ Q, const float* __restrict__ K,
    float* __restrict__ S)
{
    extern __shared__ char smem[];
    const uint32_t sb = (smem_u32(smem) + 1023u) & ~1023u;
    const uint32_t QH = sb;
    const uint32_t QL = QH + 16384;
    const uint32_t KH = QL + 16384;
    const uint32_t KL = KH + 16384;

    const int tid  = threadIdx.x;
    const int lane = tid & 31;
    const int w    = tid >> 5;
    const int wm   = (w >> 1) * 32;   // 4 warps in M
    const int wn   = (w & 1) * 64;    // 2 warps in N

    const int b  = blockIdx.z;
    const int m0 = blockIdx.y * 128;
    const int n0 = blockIdx.x * 128;

    const float* Qb = Q + (size_t)b * LQ  * DIM;
    const float* Kb = K + (size_t)b * LKV * DIM;
    float*       Sb = S + (size_t)b * LQ  * LKV;

    float acc[2][8][4] = {};

    const uint32_t a_row = lane & 15;
    const uint32_t a_kof = (lane >> 4) * 16;
    const uint32_t b_row = (lane & 7) + ((lane & 16) >> 1);
    const uint32_t b_kof = ((lane >> 3) & 1) * 16;

    for (int c = 0; c < 2; c++) {
        const int k0 = c * 64;
        if (c) __syncthreads();

        #pragma unroll
        for (int i = 0; i < 8; i++) {
            int idx = i * 256 + tid;
            int row = idx >> 4;
            int c4  = (idx & 15) * 4;
            uint32_t off = swz((uint32_t)row * 128u + (uint32_t)c4 * 2u);

            float4 q = *(const float4*)(Qb + (size_t)(m0 + row) * DIM + k0 + c4);
            q.x *= SM_SCALE; q.y *= SM_SCALE; q.z *= SM_SCALE; q.w *= SM_SCALE;
            uint2 qh, ql; split4(q, qh, ql);
            sts8(QH + off, qh);
            sts8(QL + off, ql);

            float4 kv = *(const float4*)(Kb + (size_t)(n0 + row) * DIM + k0 + c4);
            uint2 kh, kl; split4(kv, kh, kl);
            sts8(KH + off, kh);
            sts8(KL + off, kl);
        }
        __syncthreads();

        #pragma unroll
        for (int ks = 0; ks < 4; ks++) {
            const uint32_t kb = ks * 32;
            uint32_t ah[2][4], al[2][4], bb[8][2];

            #pragma unroll
            for (int mf = 0; mf < 2; mf++) {
                uint32_t ro = (uint32_t)(wm + mf * 16 + a_row) * 128u + kb + a_kof;
                ldsm4(ah[mf], QH + swz(ro));
                ldsm4(al[mf], QL + swz(ro));
            }
            #pragma unroll
            for (int j = 0; j < 4; j++) {
                uint32_t ro = (uint32_t)(wn + j * 16 + b_row) * 128u + kb + b_kof;
                ldsm4(&bb[2 * j][0], KH + swz(ro));
            }
            #pragma unroll
            for (int mf = 0; mf < 2; mf++)
                #pragma unroll
                for (int nf = 0; nf < 8; nf++) {
                    mma_bf16(acc[mf][nf], ah[mf], bb[nf]);
                    mma_bf16(acc[mf][nf], al[mf], bb[nf]);
                }
            #pragma unroll
            for (int j = 0; j < 4; j++) {
                uint32_t ro = (uint32_t)(wn + j * 16 + b_row) * 128u + kb + b_kof;
                ldsm4(&bb[2 * j][0], KL + swz(ro));
            }
            #pragma unroll
            for (int mf = 0; mf < 2; mf++)
                #pragma unroll
                for (int nf = 0; nf < 8; nf++)
                    mma_bf16(acc[mf][nf], ah[mf], bb[nf]);
        }
    }

    // epilogue: exp, store E, accumulate per-row partial sums (deterministic)
    const int er = lane >> 2;
    const int ec = (lane & 3) * 2;
    float rsum[2][2] = {{0.f, 0.f}, {0.f, 0.f}};
    #pragma unroll
    for (int mf = 0; mf < 2; mf++)
        #pragma unroll
        for (int nf = 0; nf < 8; nf++) {
            float e0 = __expf(fminf(acc[mf][nf][0], 80.f));
            float e1 = __expf(fminf(acc[mf][nf][1], 80.f));
            float e2 = __expf(fminf(acc[mf][nf][2], 80.f));
            float e3 = __expf(fminf(acc[mf][nf][3], 80.f));
            int r = m0 + wm + mf * 16 + er;
            int cc = n0 + wn + nf * 8 + ec;
            *(float2*)(Sb + (size_t)r * LKV + cc)       = make_float2(e0, e1);
            *(float2*)(Sb + (size_t)(r + 8) * LKV + cc) = make_float2(e2, e3);
            rsum[mf][0] += e0 + e1;
            rsum[mf][1] += e2 + e3;
        }
    #pragma unroll
    for (int mf = 0; mf < 2; mf++)
        #pragma unroll
        for (int h = 0; h < 2; h++) {
            float v = rsum[mf][h];
            v += __shfl_xor_sync(0xffffffffu, v, 1);
            v += __shfl_xor_sync(0xffffffffu, v, 2);
            if ((lane & 3) == 0) {
                int row = m0 + wm + mf * 16 + h * 8 + er;
                g_partial[((size_t)b * LQ + row) * 32 + blockIdx.x * 2 + (w & 1)] = v;
            }
        }
}

// ---------------------------------------------------------------------------
// GEMM2: C = diag(inv) * (E V).  CTA tile 64(M) x 128(N=DV), K=2048 in 32
// chunks of 64.  cp.async double buffer of E(fp32) + Vt hi/lo (bf16).
// Per chunk: writes normalized weights W = E*inv (final output, in place),
// splits unnormalized E -> bf16 hi/lo for 3-pass MMA.  Context scaled by inv
// in the epilogue.  NOTE: trailing __syncthreads in the chunk loop is the
// consumer-release barrier — next iteration's cp.async overwrites the V
// buffer that this chunk's MMA reads.
// ---------------------------------------------------------------------------
// smem layout (offsets from 1024-aligned base):
//   EB[2]  : +0      and +16384   (64x64 fp32, linear)
//   VH[2]  : +32768  and +49152   (128x64 bf16, swizzled)
//   VL[2]  : +65536  and +81920
//   WH     : +98304               (64x64 bf16, swizzled)
//   WL     : +106496
//   inv_s  : +114688              (64 floats)
static constexpr int G2_SMEM = 1024 + 114688 + 256;

__global__ __launch_bounds__(256, 2) void gemm2_mma_kernel(
    float* __restrict__ W, float* __restrict__ C)
{
    extern __shared__ char smem[];
    const uint32_t sb = (smem_u32(smem) + 1023u) & ~1023u;
    const uint32_t EB0 = sb;
    const uint32_t VH0 = sb + 32768u;
    const uint32_t VL0 = sb + 65536u;
    const uint32_t WHt = sb + 98304u;
    const uint32_t WLt = sb + 106496u;
    float* inv_s = (float*)(smem + (sb - smem_u32(smem)) + 114688u);

    const int tid  = threadIdx.x;
    const int lane = tid & 31;
    const int w    = tid >> 5;
    const int wm   = (w >> 2) * 32;   // 2 warps in M
    const int wn   = (w & 3) * 32;    // 4 warps in N

    const int m0 = blockIdx.x * 64;
    const int b  = blockIdx.y;

    float* Wb = W + (size_t)b * LQ * LKV + (size_t)m0 * LKV;
    const __nv_bfloat16* Vh = g_Vt_hi + (size_t)b * DIM * LKV;
    const __nv_bfloat16* Vl = g_Vt_lo + (size_t)b * DIM * LKV;
    float* Cb = C + (size_t)b * LQ * DIM;

    // row inverse sums (deterministic reduction of 32 partials)
    if (tid < 64) {
        const float* p = g_partial + ((size_t)b * LQ + m0 + tid) * 32;
        float s = 0.f;
        #pragma unroll
        for (int j = 0; j < 32; j++) s += p[j];
        inv_s[tid] = 1.0f / s;
    }

    auto load_chunk = [&](int c, int buf) {
        const int k0 = c * 64;
        const uint32_t eb = EB0 + (uint32_t)buf * 16384u;
        const uint32_t vh = VH0 + (uint32_t)buf * 16384u;
        const uint32_t vl = VL0 + (uint32_t)buf * 16384u;
        #pragma unroll
        for (int i = 0; i < 4; i++) {
            int u = i * 256 + tid;
            {   // E: 64 rows x 16 float4-units per row, linear
                int row = u >> 4, c4 = (u & 15) * 4;
                CP_ASYNC16(eb + (uint32_t)u * 16u, Wb + (size_t)row * LKV + k0 + c4);
            }
            {   // V: 128 rows x 8 bf16x8-units per row, swizzled
                int row = u >> 3, c8 = (u & 7) * 8;
                uint32_t off = swz((uint32_t)row * 128u + (uint32_t)c8 * 2u);
                CP_ASYNC16(vh + off, Vh + (size_t)row * LKV + k0 + c8);
                CP_ASYNC16(vl + off, Vl + (size_t)row * LKV + k0 + c8);
            }
        }
    };

    float acc[2][4][4] = {};

    const uint32_t a_row = lane & 15;
    const uint32_t a_kof = (lane >> 4) * 16;
    const uint32_t b_row = (lane & 7) + ((lane & 16) >> 1);
    const uint32_t b_kof = ((lane >> 3) & 1) * 16;

    load_chunk(0, 0);
    CP_COMMIT();

    for (int c = 0; c < 32; c++) {
        if (c < 31) {
            load_chunk(c + 1, (c + 1) & 1);
            CP_COMMIT();
            CP_WAIT(1);
        } else {
            CP_WAIT(0);
        }
        __syncthreads();   // chunk c data resident

        const int k0 = c * 64;
        const uint32_t eb = EB0 + (uint32_t)(c & 1) * 16384u;
        const uint32_t vh = VH0 + (uint32_t)(c & 1) * 16384u;
        const uint32_t vl = VL0 + (uint32_t)(c & 1) * 16384u;

        // convert: normalized W out (STG) + unnormalized bf16 split (STS)
        #pragma unroll
        for (int i = 0; i < 4; i++) {
            int u = i * 256 + tid;
            int row = u >> 4, c4 = (u & 15) * 4;
            float4 e;
            asm volatile("ld.shared.v4.f32 {%0,%1,%2,%3}, [%4];"
                         : "=f"(e.x), "=f"(e.y), "=f"(e.z), "=f"(e.w)
                         : "r"(eb + (uint32_t)u * 16u));
            float inv = inv_s[row];
            float4 wn4 = make_float4(e.x * inv, e.y * inv, e.z * inv, e.w * inv);
            *(float4*)(Wb + (size_t)row * LKV + k0 + c4) = wn4;
            uint2 hi, lo; split4(e, hi, lo);
            uint32_t off = swz((uint32_t)row * 128u + (uint32_t)c4 * 2u);
            sts8(WHt + off, hi);
            sts8(WLt + off, lo);
        }
        __syncthreads();   // W split visible to all warps

        #pragma unroll
        for (int ks = 0; ks < 4; ks++) {
            const uint32_t kb = ks * 32;
            uint32_t ah[2][4], al[2][4], bb[4][2];

            #pragma unroll
            for (int mf = 0; mf < 2; mf++) {
                uint32_t ro = (uint32_t)(wm + mf * 16 + a_row) * 128u + kb + a_kof;
                ldsm4(ah[mf], WHt + swz(ro));
                ldsm4(al[mf], WLt + swz(ro));
            }
            #pragma unroll
            for (int j = 0; j < 2; j++) {
                uint32_t ro = (uint32_t)(wn + j * 16 + b_row) * 128u + kb + b_kof;
                ldsm4(&bb[2 * j][0], vh + swz(ro));
            }
            #pragma unroll
            for (int mf = 0; mf < 2; mf++)
                #pragma unroll
                for (int nf = 0; nf < 4; nf++) {
                    mma_bf16(acc[mf][nf], ah[mf], bb[nf]);
                    mma_bf16(acc[mf][nf], al[mf], bb[nf]);
                }
            #pragma unroll
            for (int j = 0; j < 2; j++) {
                uint32_t ro = (uint32_t)(wn + j * 16 + b_row) * 128u + kb + b_kof;
                ldsm4(&bb[2 * j][0], vl + swz(ro));
            }
            #pragma unroll
            for (int mf = 0; mf < 2; mf++)
                #pragma unroll
                for (int nf = 0; nf < 4; nf++)
                    mma_bf16(acc[mf][nf], ah[mf], bb[nf]);
        }

        __syncthreads();   // RELEASE: all warps done reading this chunk's
                           // V/E buffers before next iter's cp.async refills
    }

    // epilogue: scale by row inverse sums, write context
    const int er = lane >> 2;
    const int ec = (lane & 3) * 2;
    #pragma unroll
    for (int mf = 0; mf < 2; mf++) {
        float i0 = inv_s[wm + mf * 16 + er];
        float i1 = inv_s[wm + mf * 16 + er + 8];
        #pragma unroll
        for (int nf = 0; nf < 4; nf++) {
            int r = m0 + wm + mf * 16 + er;
            int cc = wn + nf * 8 + ec;
            *(float2*)(Cb + (size_t)r * DIM + cc) =
                make_float2(acc[mf][nf][0] * i0, acc[mf][nf][1] * i0);
            *(float2*)(Cb + (size_t)(r + 8) * DIM + cc) =
                make_float2(acc[mf][nf][2] * i1, acc[mf][nf][3] * i1);
        }
    }
}

// ---------------------------------------------------------------------------
extern "C" void kernel_launch(void* const* d_in, const int* in_sizes, int n_in,
                              void* d_out, int out_size)
{
    const float* Q = (const float*)d_in[0];
    const float* K = (const float*)d_in[1];
    const float* V = (const float*)d_in[2];

    float* Wout = (float*)d_out;                            // (B,LQ,LKV)
    float* Cout = Wout + (size_t)BATCH * LQ * LKV;          // (B,LQ,DV)

    static bool attr_done = false;
    if (!attr_done) {
        cudaFuncSetAttribute(gemm1_mma_kernel,
            cudaFuncAttributeMaxDynamicSharedMemorySize, G1_SMEM);
        cudaFuncSetAttribute(gemm2_mma_kernel,
            cudaFuncAttributeMaxDynamicSharedMemorySize, G2_SMEM);
        attr_done = true;
    }

    dim3 gt(DIM / 32, LKV / 32, BATCH);
    vt_split_kernel<<<gt, 256>>>(V);

    dim3 g1(LKV / 128, LQ / 128, BATCH);    // 16 x 16 x 8 = 2048 CTAs
    gemm1_mma_kernel<<<g1, 256, G1_SMEM>>>(Q, K, Wout);

    dim3 g2(LQ / 64, BATCH);                // 32 x 8 = 256 CTAs
    gemm2_mma_kernel<<<g2, 256, G2_SMEM>>>(Wout, Cout);
}

// round 8
// speedup vs baseline: 3.1890x; 1.1117x over previous
#include <cuda_runtime.h>
#include <cuda_bf16.h>
#include <cstdint>

static constexpr int BATCH = 8;
static constexpr int LQ    = 2048;
static constexpr int LKV   = 2048;
static constexpr int DIM   = 128;   // D == DV == 128
static constexpr float SM_SCALE = 0.08838834764831845f; // 1/sqrt(128)

// Scratch (device globals; no runtime allocation allowed)
__device__ __align__(128) __nv_bfloat16 g_Qh[(size_t)BATCH * LQ  * DIM];
__device__ __align__(128) __nv_bfloat16 g_Ql[(size_t)BATCH * LQ  * DIM];
__device__ __align__(128) __nv_bfloat16 g_Kh[(size_t)BATCH * LKV * DIM];
__device__ __align__(128) __nv_bfloat16 g_Kl[(size_t)BATCH * LKV * DIM];
__device__ __align__(128) __nv_bfloat16 g_Vt_hi[(size_t)BATCH * DIM * LKV]; // [B][DV][LKV]
__device__ __align__(128) __nv_bfloat16 g_Vt_lo[(size_t)BATCH * DIM * LKV];
__device__ __align__(128) __nv_bfloat16 g_Eh[(size_t)BATCH * LQ * LKV];     // exp(S) hi
__device__ __align__(128) __nv_bfloat16 g_El[(size_t)BATCH * LQ * LKV];     // exp(S) lo
// per-row partial exp-sums: [B*LQ][32]  (16 n-tiles x 2 n-warps), deterministic
__device__ __align__(128) float g_partial[(size_t)BATCH * LQ * 32];

// ---------------------------------------------------------------------------
// Helpers (compute_103-safe: ldmatrix / mma.sync / cp.async only)
// ---------------------------------------------------------------------------
__device__ __forceinline__ uint32_t smem_u32(const void* p) {
    uint32_t a;
    asm("{ .reg .u64 t; cvta.to.shared.u64 t, %1; cvt.u32.u64 %0, t; }"
        : "=r"(a) : "l"(p));
    return a;
}
__device__ __forceinline__ uint32_t swz(uint32_t off) {       // SW128 swizzle
    return off ^ ((off >> 3) & 0x70);
}
__device__ __forceinline__ uint32_t pack2(__nv_bfloat16 a, __nv_bfloat16 b) {
    __nv_bfloat162 t(a, b);
    return *reinterpret_cast<uint32_t*>(&t);
}
__device__ __forceinline__ void split1(float v, __nv_bfloat16& h, __nv_bfloat16& l) {
    h = __float2bfloat16(v);
    l = __float2bfloat16(v - __bfloat162float(h));
}
__device__ __forceinline__ void split4(float4 v, uint2& hi, uint2& lo) {
    __nv_bfloat16 h0, h1, h2, h3, l0, l1, l2, l3;
    split1(v.x, h0, l0); split1(v.y, h1, l1);
    split1(v.z, h2, l2); split1(v.w, h3, l3);
    hi.x = pack2(h0, h1); hi.y = pack2(h2, h3);
    lo.x = pack2(l0, l1); lo.y = pack2(l2, l3);
}
__device__ __forceinline__ float2 bf2f(uint32_t u) {
    __nv_bfloat162 t = *reinterpret_cast<__nv_bfloat162*>(&u);
    return __bfloat1622float2(t);
}
__device__ __forceinline__ uint2 lds8(uint32_t addr) {
    uint2 v;
    asm volatile("ld.shared.v2.b32 {%0,%1}, [%2];" : "=r"(v.x), "=r"(v.y) : "r"(addr));
    return v;
}
__device__ __forceinline__ void ldsm4(uint32_t* r, uint32_t addr) {
    asm volatile("ldmatrix.sync.aligned.m8n8.x4.shared.b16 {%0,%1,%2,%3}, [%4];"
                 : "=r"(r[0]), "=r"(r[1]), "=r"(r[2]), "=r"(r[3]) : "r"(addr));
}
__device__ __forceinline__ void mma_bf16(float* d, const uint32_t* a, const uint32_t* b) {
    asm volatile("mma.sync.aligned.m16n8k16.row.col.f32.bf16.bf16.f32 "
                 "{%0,%1,%2,%3}, {%4,%5,%6,%7}, {%8,%9}, {%0,%1,%2,%3};"
                 : "+f"(d[0]), "+f"(d[1]), "+f"(d[2]), "+f"(d[3])
                 : "r"(a[0]), "r"(a[1]), "r"(a[2]), "r"(a[3]), "r"(b[0]), "r"(b[1]));
}
#define CP_ASYNC16(dst, src) \
    asm volatile("cp.async.cg.shared.global [%0], [%1], 16;" :: "r"(dst), "l"(src) : "memory")
#define CP_COMMIT()  asm volatile("cp.async.commit_group;" ::: "memory")
#define CP_WAIT(n)   asm volatile("cp.async.wait_group %0;" :: "n"(n) : "memory")

// ---------------------------------------------------------------------------
// Prep A: split Q(*scale) and K into bf16 hi/lo scratch (row-major unchanged)
// ---------------------------------------------------------------------------
__global__ __launch_bounds__(256) void qk_split_kernel(
    const float* __restrict__ Q, const float* __restrict__ K)
{
    const size_t t = (size_t)blockIdx.x * 256 + threadIdx.x;   // float4 index
    const bool isK = blockIdx.y != 0;
    const float4 v4 = ((const float4*)(isK ? K : Q))[t];
    float4 v = v4;
    if (!isK) { v.x *= SM_SCALE; v.y *= SM_SCALE; v.z *= SM_SCALE; v.w *= SM_SCALE; }
    uint2 hi, lo; split4(v, hi, lo);
    ((uint2*)(isK ? g_Kh : g_Qh))[t] = hi;
    ((uint2*)(isK ? g_Kl : g_Ql))[t] = lo;
}

// ---------------------------------------------------------------------------
// Prep B: transpose + bf16-split V:  V[b][k][n] -> Vt_hi/lo[b][n][k]
// ---------------------------------------------------------------------------
__global__ __launch_bounds__(256) void vt_split_kernel(const float* __restrict__ V)
{
    __shared__ float t[32][33];
    const int b  = blockIdx.z;
    const int k0 = blockIdx.y * 32;
    const int n0 = blockIdx.x * 32;
    const int tx = threadIdx.x & 31;
    const int ty = threadIdx.x >> 5;   // 0..7

    #pragma unroll
    for (int i = 0; i < 4; i++) {
        int k = ty + i * 8;
        t[k][tx] = V[((size_t)b * LKV + k0 + k) * DIM + n0 + tx];
    }
    __syncthreads();
    #pragma unroll
    for (int i = 0; i < 4; i++) {
        int n = ty + i * 8;
        float x = t[tx][n];
        __nv_bfloat16 h, l;
        split1(x, h, l);
        size_t o = ((size_t)b * DIM + n0 + n) * LKV + k0 + tx;
        g_Vt_hi[o] = h;
        g_Vt_lo[o] = l;
    }
}

// ---------------------------------------------------------------------------
// GEMM1: E = exp((Q*scale) K^T) via mma.sync bf16x3, pure-bf16 operands.
// CTA tile 128x128, 8 warps (warp tile 32x64).  K=128 in 2 chunks of 64,
// single 64KB buffer, cp.async loads.  Writes Eh/El bf16 + partial sums.
// ---------------------------------------------------------------------------
static constexpr int G1_SMEM = 1024 + 4 * 16384;

__global__ __launch_bounds__(256, 2) void gemm1_mma_kernel()
{
    extern __shared__ char smem[];
    const uint32_t sb = (smem_u32(smem) + 1023u) & ~1023u;
    const uint32_t QH = sb;
    const uint32_t QL = QH + 16384;
    const uint32_t KH = QL + 16384;
    const uint32_t KL = KH + 16384;

    const int tid  = threadIdx.x;
    const int lane = tid & 31;
    const int w    = tid >> 5;
    const int wm   = (w >> 1) * 32;   // 4 warps in M
    const int wn   = (w & 1) * 64;    // 2 warps in N

    const int b  = blockIdx.z;
    const int m0 = blockIdx.y * 128;
    const int n0 = blockIdx.x * 128;

    const __nv_bfloat16* Qh = g_Qh + ((size_t)b * LQ  + m0) * DIM;
    const __nv_bfloat16* Ql = g_Ql + ((size_t)b * LQ  + m0) * DIM;
    const __nv_bfloat16* Kh = g_Kh + ((size_t)b * LKV + n0) * DIM;
    const __nv_bfloat16* Kl = g_Kl + ((size_t)b * LKV + n0) * DIM;

    float acc[2][8][4] = {};

    const uint32_t a_row = lane & 15;
    const uint32_t a_kof = (lane >> 4) * 16;
    const uint32_t b_row = (lane & 7) + ((lane & 16) >> 1);
    const uint32_t b_kof = ((lane >> 3) & 1) * 16;

    for (int c = 0; c < 2; c++) {
        const int k0 = c * 64;
        if (c) __syncthreads();   // all warps done with chunk-0 smem

        #pragma unroll
        for (int i = 0; i < 4; i++) {
            int u = i * 256 + tid;
            int row = u >> 3, c8 = (u & 7) * 8;
            uint32_t off = swz((uint32_t)row * 128u + (uint32_t)c8 * 2u);
            CP_ASYNC16(QH + off, Qh + (size_t)row * DIM + k0 + c8);
            CP_ASYNC16(QL + off, Ql + (size_t)row * DIM + k0 + c8);
            CP_ASYNC16(KH + off, Kh + (size_t)row * DIM + k0 + c8);
            CP_ASYNC16(KL + off, Kl + (size_t)row * DIM + k0 + c8);
        }
        CP_COMMIT();
        CP_WAIT(0);
        __syncthreads();

        #pragma unroll
        for (int ks = 0; ks < 4; ks++) {
            const uint32_t kb = ks * 32;
            uint32_t ah[2][4], al[2][4], bb[8][2];

            #pragma unroll
            for (int mf = 0; mf < 2; mf++) {
                uint32_t ro = (uint32_t)(wm + mf * 16 + a_row) * 128u + kb + a_kof;
                ldsm4(ah[mf], QH + swz(ro));
                ldsm4(al[mf], QL + swz(ro));
            }
            #pragma unroll
            for (int j = 0; j < 4; j++) {
                uint32_t ro = (uint32_t)(wn + j * 16 + b_row) * 128u + kb + b_kof;
                ldsm4(&bb[2 * j][0], KH + swz(ro));
            }
            #pragma unroll
            for (int mf = 0; mf < 2; mf++)
                #pragma unroll
                for (int nf = 0; nf < 8; nf++) {
                    mma_bf16(acc[mf][nf], ah[mf], bb[nf]);
                    mma_bf16(acc[mf][nf], al[mf], bb[nf]);
                }
            #pragma unroll
            for (int j = 0; j < 4; j++) {
                uint32_t ro = (uint32_t)(wn + j * 16 + b_row) * 128u + kb + b_kof;
                ldsm4(&bb[2 * j][0], KL + swz(ro));
            }
            #pragma unroll
            for (int mf = 0; mf < 2; mf++)
                #pragma unroll
                for (int nf = 0; nf < 8; nf++)
                    mma_bf16(acc[mf][nf], ah[mf], bb[nf]);
        }
    }

    // epilogue: exp, split to bf16 hi/lo, store; per-row partial sums
    const int er = lane >> 2;
    const int ec = (lane & 3) * 2;
    float rsum[2][2] = {{0.f, 0.f}, {0.f, 0.f}};
    #pragma unroll
    for (int mf = 0; mf < 2; mf++)
        #pragma unroll
        for (int nf = 0; nf < 8; nf++) {
            float e0 = __expf(fminf(acc[mf][nf][0], 80.f));
            float e1 = __expf(fminf(acc[mf][nf][1], 80.f));
            float e2 = __expf(fminf(acc[mf][nf][2], 80.f));
            float e3 = __expf(fminf(acc[mf][nf][3], 80.f));
            int r = m0 + wm + mf * 16 + er;
            int cc = n0 + wn + nf * 8 + ec;
            __nv_bfloat16 h0, l0, h1, l1;
            split1(e0, h0, l0); split1(e1, h1, l1);
            *(uint32_t*)(g_Eh + ((size_t)b * LQ + r) * LKV + cc) = pack2(h0, h1);
            *(uint32_t*)(g_El + ((size_t)b * LQ + r) * LKV + cc) = pack2(l0, l1);
            split1(e2, h0, l0); split1(e3, h1, l1);
            *(uint32_t*)(g_Eh + ((size_t)b * LQ + r + 8) * LKV + cc) = pack2(h0, h1);
            *(uint32_t*)(g_El + ((size_t)b * LQ + r + 8) * LKV + cc) = pack2(l0, l1);
            rsum[mf][0] += e0 + e1;
            rsum[mf][1] += e2 + e3;
        }
    #pragma unroll
    for (int mf = 0; mf < 2; mf++)
        #pragma unroll
        for (int h = 0; h < 2; h++) {
            float v = rsum[mf][h];
            v += __shfl_xor_sync(0xffffffffu, v, 1);
            v += __shfl_xor_sync(0xffffffffu, v, 2);
            if ((lane & 3) == 0) {
                int row = m0 + wm + mf * 16 + h * 8 + er;
                g_partial[((size_t)b * LQ + row) * 32 + blockIdx.x * 2 + (w & 1)] = v;
            }
        }
}

// ---------------------------------------------------------------------------
// GEMM2: C = diag(inv) * (E V), and W = E*inv written as final fp32 weights.
// CTA tile 64(M) x 128(N=DV), K=2048 in 32 chunks of 64.  Pure bf16 MMA
// operands (Eh/El from gemm1, Vt hi/lo), cp.async double buffer,
// ONE barrier per chunk: prefetch(c+1) issued after the barrier proves all
// warps left chunk c-1, so its buffer overwrite is race-free.
// ---------------------------------------------------------------------------
// per buffer (48KB): EH 8KB, EL 8KB (64x64 bf16), VH 16KB, VL 16KB (128x64)
static constexpr int G2_SMEM = 1024 + 2 * 49152 + 256;

__global__ __launch_bounds__(256, 2) void gemm2_mma_kernel(
    float* __restrict__ W, float* __restrict__ C)
{
    extern __shared__ char smem[];
    const uint32_t sb = (smem_u32(smem) + 1023u) & ~1023u;
    float* inv_s = (float*)(smem + (sb - smem_u32(smem)) + 2 * 49152);

    const int tid  = threadIdx.x;
    const int lane = tid & 31;
    const int w    = tid >> 5;
    const int wm   = (w >> 2) * 32;   // 2 warps in M
    const int wn   = (w & 3) * 32;    // 4 warps in N

    const int m0 = blockIdx.x * 64;
    const int b  = blockIdx.y;

    float* Wb = W + ((size_t)b * LQ + m0) * LKV;
    const __nv_bfloat16* Eh = g_Eh + ((size_t)b * LQ + m0) * LKV;
    const __nv_bfloat16* El = g_El + ((size_t)b * LQ + m0) * LKV;
    const __nv_bfloat16* Vh = g_Vt_hi + (size_t)b * DIM * LKV;
    const __nv_bfloat16* Vl = g_Vt_lo + (size_t)b * DIM * LKV;
    float* Cb = C + (size_t)b * LQ * DIM;

    // row inverse sums (deterministic reduction of 32 partials)
    if (tid < 64) {
        const float* p = g_partial + ((size_t)b * LQ + m0 + tid) * 32;
        float s = 0.f;
        #pragma unroll
        for (int j = 0; j < 32; j++) s += p[j];
        inv_s[tid] = 1.0f / s;
    }

    auto load_chunk = [&](int c, int buf) {
        const int k0 = c * 64;
        const uint32_t base = sb + (uint32_t)buf * 49152u;
        #pragma unroll
        for (int i = 0; i < 2; i++) {       // E tiles: 64 rows x 8 units
            int u = i * 256 + tid;
            int row = u >> 3, c8 = (u & 7) * 8;
            uint32_t off = swz((uint32_t)row * 128u + (uint32_t)c8 * 2u);
            CP_ASYNC16(base + off,          Eh + (size_t)row * LKV + k0 + c8);
            CP_ASYNC16(base + 8192u + off,  El + (size_t)row * LKV + k0 + c8);
        }
        #pragma unroll
        for (int i = 0; i < 4; i++) {       // V tiles: 128 rows x 8 units
            int u = i * 256 + tid;
            int row = u >> 3, c8 = (u & 7) * 8;
            uint32_t off = swz((uint32_t)row * 128u + (uint32_t)c8 * 2u);
            CP_ASYNC16(base + 16384u + off, Vh + (size_t)row * LKV + k0 + c8);
            CP_ASYNC16(base + 32768u + off, Vl + (size_t)row * LKV + k0 + c8);
        }
    };

    float acc[2][4][4] = {};

    const uint32_t a_row = lane & 15;
    const uint32_t a_kof = (lane >> 4) * 16;
    const uint32_t b_row = (lane & 7) + ((lane & 16) >> 1);
    const uint32_t b_kof = ((lane >> 3) & 1) * 16;

    load_chunk(0, 0);
    CP_COMMIT();

    for (int c = 0; c < 32; c++) {
        CP_WAIT(0);
        __syncthreads();   // buf[c&1] resident; all warps past chunk c-1

        if (c < 31) { load_chunk(c + 1, (c + 1) & 1); CP_COMMIT(); }

        const int k0 = c * 64;
        const uint32_t base = sb + (uint32_t)(c & 1) * 49152u;
        const uint32_t EHt = base, ELt = base + 8192u;
        const uint32_t vh = base + 16384u, vl = base + 32768u;

        // W = (Eh + El) * inv  -> final fp32 weights (STGs drain during MMA)
        #pragma unroll
        for (int i = 0; i < 4; i++) {
            int u = i * 256 + tid;
            int row = u >> 4, c4 = (u & 15) * 4;
            uint32_t off = swz((uint32_t)row * 128u + (uint32_t)c4 * 2u);
            uint2 hh = lds8(EHt + off);
            uint2 ll = lds8(ELt + off);
            float2 h01 = bf2f(hh.x), h23 = bf2f(hh.y);
            float2 l01 = bf2f(ll.x), l23 = bf2f(ll.y);
            float inv = inv_s[row];
            float4 wv = make_float4((h01.x + l01.x) * inv, (h01.y + l01.y) * inv,
                                    (h23.x + l23.x) * inv, (h23.y + l23.y) * inv);
            *(float4*)(Wb + (size_t)row * LKV + k0 + c4) = wv;
        }

        #pragma unroll
        for (int ks = 0; ks < 4; ks++) {
            const uint32_t kb = ks * 32;
            uint32_t ah[2][4], al[2][4], bb[4][2];

            #pragma unroll
            for (int mf = 0; mf < 2; mf++) {
                uint32_t ro = (uint32_t)(wm + mf * 16 + a_row) * 128u + kb + a_kof;
                ldsm4(ah[mf], EHt + swz(ro));
                ldsm4(al[mf], ELt + swz(ro));
            }
            #pragma unroll
            for (int j = 0; j < 2; j++) {
                uint32_t ro = (uint32_t)(wn + j * 16 + b_row) * 128u + kb + b_kof;
                ldsm4(&bb[2 * j][0], vh + swz(ro));
            }
            #pragma unroll
            for (int mf = 0; mf < 2; mf++)
                #pragma unroll
                for (int nf = 0; nf < 4; nf++) {
                    mma_bf16(acc[mf][nf], ah[mf], bb[nf]);
                    mma_bf16(acc[mf][nf], al[mf], bb[nf]);
                }
            #pragma unroll
            for (int j = 0; j < 2; j++) {
                uint32_t ro = (uint32_t)(wn + j * 16 + b_row) * 128u + kb + b_kof;
                ldsm4(&bb[2 * j][0], vl + swz(ro));
            }
            #pragma unroll
            for (int mf = 0; mf < 2; mf++)
                #pragma unroll
                for (int nf = 0; nf < 4; nf++)
                    mma_bf16(acc[mf][nf], ah[mf], bb[nf]);
        }
    }

    // epilogue: scale by row inverse sums, write context
    const int er = lane >> 2;
    const int ec = (lane & 3) * 2;
    #pragma unroll
    for (int mf = 0; mf < 2; mf++) {
        float i0 = inv_s[wm + mf * 16 + er];
        float i1 = inv_s[wm + mf * 16 + er + 8];
        #pragma unroll
        for (int nf = 0; nf < 4; nf++) {
            int r = m0 + wm + mf * 16 + er;
            int cc = wn + nf * 8 + ec;
            *(float2*)(Cb + (size_t)r * DIM + cc) =
                make_float2(acc[mf][nf][0] * i0, acc[mf][nf][1] * i0);
            *(float2*)(Cb + (size_t)(r + 8) * DIM + cc) =
                make_float2(acc[mf][nf][2] * i1, acc[mf][nf][3] * i1);
        }
    }
}

// ---------------------------------------------------------------------------
extern "C" void kernel_launch(void* const* d_in, const int* in_sizes, int n_in,
                              void* d_out, int out_size)
{
    const float* Q = (const float*)d_in[0];
    const float* K = (const float*)d_in[1];
    const float* V = (const float*)d_in[2];

    float* Wout = (float*)d_out;                            // (B,LQ,LKV)
    float* Cout = Wout + (size_t)BATCH * LQ * LKV;          // (B,LQ,DV)

    static bool attr_done = false;
    if (!attr_done) {
        cudaFuncSetAttribute(gemm1_mma_kernel,
            cudaFuncAttributeMaxDynamicSharedMemorySize, G1_SMEM);
        cudaFuncSetAttribute(gemm2_mma_kernel,
            cudaFuncAttributeMaxDynamicSharedMemorySize, G2_SMEM);
        attr_done = true;
    }

    dim3 gq((unsigned)((size_t)BATCH * LQ * DIM / 4 / 256), 2);
    qk_split_kernel<<<gq, 256>>>(Q, K);

    dim3 gt(DIM / 32, LKV / 32, BATCH);
    vt_split_kernel<<<gt, 256>>>(V);

    dim3 g1(LKV / 128, LQ / 128, BATCH);    // 16 x 16 x 8 = 2048 CTAs
    gemm1_mma_kernel<<<g1, 256, G1_SMEM>>>();

    dim3 g2(LQ / 64, BATCH);                // 32 x 8 = 256 CTAs
    gemm2_mma_kernel<<<g2, 256, G2_SMEM>>>(Wout, Cout);
}